// round 11
// baseline (speedup 1.0000x reference)
#include <cuda_runtime.h>

// ---------------------------------------------------------------------------
// TalkerAttentionV2: single-token GQA decode attention + full KV-cache copy.
// B=16, HID=1024, NH=16, NKV=8, HD=128, S=4096.
// R11 = R10 with SC 8->4: 512 chunk blocks <= 740 resident CTAs -> single
// wave, no tail. Phase 1 reverts to the R2 k_scores structure (one float4
// column per thread, full-HD loop, no cross-thread d-split).
// No cache hints (regressed 2x); no occupancy caps on k_attn (register cliff).
// ---------------------------------------------------------------------------

namespace {
constexpr int B    = 16;
constexpr int HID  = 1024;
constexpr int NH   = 16;
constexpr int NKV  = 8;
constexpr int HD   = 128;
constexpr int S    = 4096;
constexpr int DKV  = NKV * HD;          // 1024
constexpr int NQ   = NH * HD;           // 2048
constexpr int QKV_ROWS = NQ + 2 * DKV;  // 4096
constexpr float EPS = 1e-6f;
constexpr float SCALE = 0.0883883476483184405f; // 128^-0.5
constexpr int SC   = 4;                 // S chunks per (b,kvh) -> 512 blocks
constexpr int SLEN = S / SC;            // 1024
constexpr int CF4  = SLEN / 4;          // 256 float4 columns per chunk
}

// Scratch (static device globals)
__device__ __align__(16) float g_qkv[B][QKV_ROWS];      // raw q|k|v projections
__device__ __align__(16) float g_q[B][NH][HD];          // normed+roped q
__device__ __align__(16) float g_kn[B][NKV][HD];        // normed+roped new k
__device__ __align__(16) float g_pout[B][NH][SC][HD];   // partial V-weighted sums
__device__ __align__(16) float2 g_ms[B][NH][SC];        // per-chunk (max, sumexp)
__device__ __align__(16) float g_attnout[B][NQ];        // combined attention out
__device__ int g_pos[B];

// ---------------------------------------------------------------------------
// 1. QKV projection: one block per output row (4096 rows), 16 batches at once
// ---------------------------------------------------------------------------
__global__ void k_qkv(const float* __restrict__ x,
                      const float* __restrict__ Wq,
                      const float* __restrict__ Wk,
                      const float* __restrict__ Wv) {
    int r = blockIdx.x;
    const float* wrow;
    if (r < NQ)            wrow = Wq + (size_t)r * HID;
    else if (r < NQ + DKV) wrow = Wk + (size_t)(r - NQ) * HID;
    else                   wrow = Wv + (size_t)(r - NQ - DKV) * HID;

    const float4* w4 = (const float4*)wrow;
    const float4* x4 = (const float4*)x;

    float acc[B];
#pragma unroll
    for (int b = 0; b < B; b++) acc[b] = 0.0f;

#pragma unroll
    for (int i = 0; i < 2; i++) {
        int k = threadIdx.x + i * 128;      // 256 float4 per row
        float4 w = w4[k];
#pragma unroll
        for (int b = 0; b < B; b++) {
            float4 xv = x4[b * (HID / 4) + k];
            acc[b] += w.x * xv.x + w.y * xv.y + w.z * xv.z + w.w * xv.w;
        }
    }

    __shared__ float red[4][B];
    int lane = threadIdx.x & 31, warp = threadIdx.x >> 5;
#pragma unroll
    for (int b = 0; b < B; b++) {
        float v = acc[b];
#pragma unroll
        for (int o = 16; o; o >>= 1) v += __shfl_xor_sync(0xffffffffu, v, o);
        if (lane == 0) red[warp][b] = v;
    }
    __syncthreads();
    if (threadIdx.x < B) {
        float v = red[0][threadIdx.x] + red[1][threadIdx.x] +
                  red[2][threadIdx.x] + red[3][threadIdx.x];
        g_qkv[threadIdx.x][r] = v;
    }
}

// ---------------------------------------------------------------------------
// 2. RMSNorm + RoPE for q and k heads; h==0 blocks also scan the one-hot
//    update mask for pos[b]. One block per (b, head), 128 threads.
// ---------------------------------------------------------------------------
__global__ void k_normrope(const float* __restrict__ cosb,
                           const float* __restrict__ sinb,
                           const float* __restrict__ qw,
                           const float* __restrict__ kw,
                           const float* __restrict__ um) {
    int b = blockIdx.x / (NH + NKV);
    int h = blockIdx.x % (NH + NKV);
    int d = threadIdx.x;

    if (h == 0) {
        for (int s = d; s < S; s += HD)
            if (um[b * S + s] > 0.5f) g_pos[b] = s;
    }

    bool isq = (h < NH);
    float t = isq ? g_qkv[b][h * HD + d]
                  : g_qkv[b][NQ + (h - NH) * HD + d];

    float sq = t * t;
#pragma unroll
    for (int o = 16; o; o >>= 1) sq += __shfl_xor_sync(0xffffffffu, sq, o);
    __shared__ float sred[4];
    __shared__ float sn[HD];
    if ((d & 31) == 0) sred[d >> 5] = sq;
    __syncthreads();
    float tot = sred[0] + sred[1] + sred[2] + sred[3];
    float w = isq ? qw[d] : kw[d];
    float n = t * rsqrtf(tot * (1.0f / HD) + EPS) * w;
    sn[d] = n;
    __syncthreads();
    float rot = (d < HD / 2) ? -sn[d + HD / 2] : sn[d - HD / 2];
    float outv = n * cosb[b * HD + d] + rot * sinb[b * HD + d];
    if (isq) g_q[b][h][d] = outv;
    else     g_kn[b][h - NH][d] = outv;
}

// ---------------------------------------------------------------------------
// 3. Fused flash-decode chunk kernel. Grid B*NKV*SC = 512, 256 threads.
//    512 blocks <= 740 resident -> single wave, no tail.
// ---------------------------------------------------------------------------
__global__ __launch_bounds__(256) void k_attn(const float* __restrict__ kcache,
                                              const float* __restrict__ vcache,
                                              const float* __restrict__ kpm,
                                              float* __restrict__ outk,
                                              float* __restrict__ outv) {
    int id    = blockIdx.x;
    int chunk = id & (SC - 1);
    int kvh   = (id >> 2) & (NKV - 1);
    int b     = id >> 5;
    int s0    = chunk * SLEN;
    int t     = threadIdx.x;   // 256

    __shared__ float q0s[HD], q1s[HD], kns[HD], vns[HD];
    __shared__ __align__(16) float e0[SLEN], e1[SLEN];
    __shared__ float sr0[8], sr1[8];

    if (t < HD) {
        q0s[t] = g_q[b][2 * kvh][t];
        q1s[t] = g_q[b][2 * kvh + 1][t];
        kns[t] = g_kn[b][kvh][t];
        vns[t] = g_qkv[b][NQ + DKV + kvh * HD + t];
    }
    __syncthreads();

    int posb = g_pos[b];
    size_t rowbase = ((size_t)(b * DKV + kvh * HD) * S + s0) >> 2; // float4 idx

    // ---- Phase 1: K copy + scores. Thread t owns float4 column t (256 cols),
    //      loops all HD=128 rows (R2 k_scores structure: proven 74% DRAM).
    {
        int c   = t;                 // 0..CF4-1
        int gs  = s0 + (c << 2);
        int rel = posb - gs;
        const float4* src = (const float4*)kcache + rowbase + c;
        float4*       dst = (float4*)outk + rowbase + c;

        float a00 = 0, a01 = 0, a02 = 0, a03 = 0;
        float a10 = 0, a11 = 0, a12 = 0, a13 = 0;
#pragma unroll 4
        for (int d = 0; d < HD; d++) {
            float4 v = src[(size_t)d * (S / 4)];
            if ((unsigned)rel < 4u) (&v.x)[rel] = kns[d];
            dst[(size_t)d * (S / 4)] = v;
            float q0 = q0s[d], q1 = q1s[d];
            a00 += q0 * v.x; a01 += q0 * v.y; a02 += q0 * v.z; a03 += q0 * v.w;
            a10 += q1 * v.x; a11 += q1 * v.y; a12 += q1 * v.z; a13 += q1 * v.w;
        }

        float4 m = *(const float4*)(kpm + (size_t)b * S + gs);
        *(float4*)&e0[c << 2] = make_float4(
            a00 * SCALE + m.x, a01 * SCALE + m.y,
            a02 * SCALE + m.z, a03 * SCALE + m.w);
        *(float4*)&e1[c << 2] = make_float4(
            a10 * SCALE + m.x, a11 * SCALE + m.y,
            a12 * SCALE + m.z, a13 * SCALE + m.w);
        __syncthreads();
    }

    // ---- Phase 2: local softmax over the chunk (two heads)
    {
        float m0 = -1e30f, m1 = -1e30f;
        for (int s = t; s < SLEN; s += 256) {
            m0 = fmaxf(m0, e0[s]);
            m1 = fmaxf(m1, e1[s]);
        }
#pragma unroll
        for (int o = 16; o; o >>= 1) {
            m0 = fmaxf(m0, __shfl_xor_sync(0xffffffffu, m0, o));
            m1 = fmaxf(m1, __shfl_xor_sync(0xffffffffu, m1, o));
        }
        if ((t & 31) == 0) { sr0[t >> 5] = m0; sr1[t >> 5] = m1; }
        __syncthreads();
        m0 = sr0[0]; m1 = sr1[0];
#pragma unroll
        for (int w = 1; w < 8; w++) {
            m0 = fmaxf(m0, sr0[w]);
            m1 = fmaxf(m1, sr1[w]);
        }
        __syncthreads();

        float s0a = 0.0f, s1a = 0.0f;
        for (int s = t; s < SLEN; s += 256) {
            float x0 = __expf(e0[s] - m0); e0[s] = x0; s0a += x0;
            float x1 = __expf(e1[s] - m1); e1[s] = x1; s1a += x1;
        }
#pragma unroll
        for (int o = 16; o; o >>= 1) {
            s0a += __shfl_xor_sync(0xffffffffu, s0a, o);
            s1a += __shfl_xor_sync(0xffffffffu, s1a, o);
        }
        if ((t & 31) == 0) { sr0[t >> 5] = s0a; sr1[t >> 5] = s1a; }
        __syncthreads();
        if (t == 0) {
            float t0 = 0, t1 = 0;
#pragma unroll
            for (int w = 0; w < 8; w++) { t0 += sr0[w]; t1 += sr1[w]; }
            g_ms[b][2 * kvh][chunk]     = make_float2(m0, t0);
            g_ms[b][2 * kvh + 1][chunk] = make_float2(m1, t1);
        }
        __syncthreads();
    }

    // ---- Phase 3: V copy + partial weighted sums. Warp w owns d rows w,w+8,..
    //      e0/e1 read as float4 (LDS.128, conflict-free). 8 loads in flight/d.
    {
        int warp = t >> 5, lane = t & 31;
        const float4* src = (const float4*)vcache + rowbase;
        float4*       dst = (float4*)outv + rowbase;

        for (int d = warp; d < HD; d += 8) {
            float p0 = 0.0f, p1 = 0.0f;
            size_t rb = (size_t)d * (S / 4);
#pragma unroll
            for (int it = 0; it < CF4 / 32; it++) {
                int si = it * 32 + lane;
                float4 v = src[rb + si];
                int sl = si << 2;
                int rel = posb - (s0 + sl);
                if ((unsigned)rel < 4u) (&v.x)[rel] = vns[d];
                dst[rb + si] = v;
                float4 w0 = *(const float4*)&e0[sl];
                float4 w1 = *(const float4*)&e1[sl];
                p0 += w0.x * v.x + w0.y * v.y + w0.z * v.z + w0.w * v.w;
                p1 += w1.x * v.x + w1.y * v.y + w1.z * v.z + w1.w * v.w;
            }
#pragma unroll
            for (int o = 16; o; o >>= 1) {
                p0 += __shfl_xor_sync(0xffffffffu, p0, o);
                p1 += __shfl_xor_sync(0xffffffffu, p1, o);
            }
            if (lane == 0) {
                g_pout[b][2 * kvh][chunk][d]     = p0;
                g_pout[b][2 * kvh + 1][chunk][d] = p1;
            }
        }
    }
}

// ---------------------------------------------------------------------------
// 4. Combine partial-softmax chunks. Grid B*NH, 128 threads (one per d).
// ---------------------------------------------------------------------------
__global__ void k_combine() {
    int b = blockIdx.x >> 4, h = blockIdx.x & (NH - 1);
    int d = threadIdx.x;

    float2 ms[SC];
    float po[SC];
    float M = -1e30f;
#pragma unroll
    for (int c = 0; c < SC; c++) {
        ms[c] = g_ms[b][h][c];
        po[c] = g_pout[b][h][c][d];
        M = fmaxf(M, ms[c].x);
    }
    float tot = 0.0f, acc = 0.0f;
#pragma unroll
    for (int c = 0; c < SC; c++) {
        float w = __expf(ms[c].x - M);
        tot += w * ms[c].y;
        acc += w * po[c];
    }
    g_attnout[b][h * HD + d] = acc / tot;
}

// ---------------------------------------------------------------------------
// 5. Output projection, smem-tiled. Grid HID/8 = 128 blocks, 256 threads.
// ---------------------------------------------------------------------------
__global__ __launch_bounds__(256) void k_oproj(const float* __restrict__ Wo,
                                               float* __restrict__ out) {
    int warp = threadIdx.x >> 5, lane = threadIdx.x & 31;
    int j = blockIdx.x * 8 + warp;
    const float4* w4 = (const float4*)(Wo + (size_t)j * NQ);

    __shared__ __align__(16) float4 s_att[B][128];   // one quarter: 32 KB

    float acc[B];
#pragma unroll
    for (int b = 0; b < B; b++) acc[b] = 0.0f;

#pragma unroll
    for (int q = 0; q < 4; q++) {
        __syncthreads();   // previous quarter fully consumed before overwrite
        for (int i = threadIdx.x; i < B * 128; i += 256) {
            int b = i >> 7, c = i & 127;
            s_att[b][c] = *(const float4*)&g_attnout[b][q * 512 + (c << 2)];
        }
        __syncthreads();
#pragma unroll
        for (int i = 0; i < 4; i++) {
            float4 w = w4[q * 128 + i * 32 + lane];
#pragma unroll
            for (int b = 0; b < B; b++) {
                float4 a = s_att[b][i * 32 + lane];
                acc[b] += w.x * a.x + w.y * a.y + w.z * a.z + w.w * a.w;
            }
        }
    }

#pragma unroll
    for (int b = 0; b < B; b++) {
        float v = acc[b];
#pragma unroll
        for (int o = 16; o; o >>= 1) v += __shfl_xor_sync(0xffffffffu, v, o);
        acc[b] = v;
    }
    if (lane == 0) {
#pragma unroll
        for (int b = 0; b < B; b++) out[b * HID + j] = acc[b];
    }
}

// ---------------------------------------------------------------------------
// Launch
// ---------------------------------------------------------------------------
extern "C" void kernel_launch(void* const* d_in, const int* in_sizes, int n_in,
                              void* d_out, int out_size) {
    (void)in_sizes; (void)n_in; (void)out_size;
    const float* x   = (const float*)d_in[0];
    const float* rc  = (const float*)d_in[1];
    const float* rs  = (const float*)d_in[2];
    const float* kpm = (const float*)d_in[3];
    const float* um  = (const float*)d_in[4];
    const float* kc  = (const float*)d_in[5];
    const float* vc  = (const float*)d_in[6];
    const float* Wq  = (const float*)d_in[7];
    const float* Wk  = (const float*)d_in[8];
    const float* Wv  = (const float*)d_in[9];
    const float* Wo  = (const float*)d_in[10];
    const float* qw  = (const float*)d_in[11];
    const float* kw  = (const float*)d_in[12];

    float* out  = (float*)d_out;
    float* outk = out + (size_t)B * HID;
    float* outv = outk + (size_t)B * DKV * S;

    k_qkv<<<QKV_ROWS, 128>>>(x, Wq, Wk, Wv);
    k_normrope<<<B * (NH + NKV), HD>>>(rc, rs, qw, kw, um);
    k_attn<<<B * NKV * SC, 256>>>(kc, vc, kpm, outk, outv);
    k_combine<<<B * NH, HD>>>();
    k_oproj<<<HID / 8, 256>>>(Wo, out);
}

// round 12
// speedup vs baseline: 1.0033x; 1.0033x over previous
#include <cuda_runtime.h>

// ---------------------------------------------------------------------------
// TalkerAttentionV2: single-token GQA decode attention + full KV-cache copy.
// B=16, HID=1024, NH=16, NKV=8, HD=128, S=4096.
// R12 = R11 + combine fused into k_attn tail via last-block election
//       (retrying R9's fusion WITHOUT the __ldcs that confounded it).
// No cache hints (regressed 2x); no occupancy caps on k_attn (register cliff).
// ---------------------------------------------------------------------------

namespace {
constexpr int B    = 16;
constexpr int HID  = 1024;
constexpr int NH   = 16;
constexpr int NKV  = 8;
constexpr int HD   = 128;
constexpr int S    = 4096;
constexpr int DKV  = NKV * HD;          // 1024
constexpr int NQ   = NH * HD;           // 2048
constexpr int QKV_ROWS = NQ + 2 * DKV;  // 4096
constexpr float EPS = 1e-6f;
constexpr float SCALE = 0.0883883476483184405f; // 128^-0.5
constexpr int SC   = 4;                 // S chunks per (b,kvh) -> 512 blocks
constexpr int SLEN = S / SC;            // 1024
constexpr int CF4  = SLEN / 4;          // 256 float4 columns per chunk
}

// Scratch (static device globals)
__device__ __align__(16) float g_qkv[B][QKV_ROWS];      // raw q|k|v projections
__device__ __align__(16) float g_q[B][NH][HD];          // normed+roped q
__device__ __align__(16) float g_kn[B][NKV][HD];        // normed+roped new k
__device__ __align__(16) float g_pout[B][NH][SC][HD];   // partial V-weighted sums
__device__ __align__(16) float2 g_ms[B][NH][SC];        // per-chunk (max, sumexp)
__device__ __align__(16) float g_attnout[B][NQ];        // combined attention out
__device__ int g_pos[B];
__device__ int g_cnt[B][NKV];                           // zero-init; elected block resets

// ---------------------------------------------------------------------------
// 1. QKV projection: one block per output row (4096 rows), 16 batches at once
// ---------------------------------------------------------------------------
__global__ void k_qkv(const float* __restrict__ x,
                      const float* __restrict__ Wq,
                      const float* __restrict__ Wk,
                      const float* __restrict__ Wv) {
    int r = blockIdx.x;
    const float* wrow;
    if (r < NQ)            wrow = Wq + (size_t)r * HID;
    else if (r < NQ + DKV) wrow = Wk + (size_t)(r - NQ) * HID;
    else                   wrow = Wv + (size_t)(r - NQ - DKV) * HID;

    const float4* w4 = (const float4*)wrow;
    const float4* x4 = (const float4*)x;

    float acc[B];
#pragma unroll
    for (int b = 0; b < B; b++) acc[b] = 0.0f;

#pragma unroll
    for (int i = 0; i < 2; i++) {
        int k = threadIdx.x + i * 128;      // 256 float4 per row
        float4 w = w4[k];
#pragma unroll
        for (int b = 0; b < B; b++) {
            float4 xv = x4[b * (HID / 4) + k];
            acc[b] += w.x * xv.x + w.y * xv.y + w.z * xv.z + w.w * xv.w;
        }
    }

    __shared__ float red[4][B];
    int lane = threadIdx.x & 31, warp = threadIdx.x >> 5;
#pragma unroll
    for (int b = 0; b < B; b++) {
        float v = acc[b];
#pragma unroll
        for (int o = 16; o; o >>= 1) v += __shfl_xor_sync(0xffffffffu, v, o);
        if (lane == 0) red[warp][b] = v;
    }
    __syncthreads();
    if (threadIdx.x < B) {
        float v = red[0][threadIdx.x] + red[1][threadIdx.x] +
                  red[2][threadIdx.x] + red[3][threadIdx.x];
        g_qkv[threadIdx.x][r] = v;
    }
}

// ---------------------------------------------------------------------------
// 2. RMSNorm + RoPE for q and k heads; h==0 blocks also scan the one-hot
//    update mask for pos[b]. One block per (b, head), 128 threads.
// ---------------------------------------------------------------------------
__global__ void k_normrope(const float* __restrict__ cosb,
                           const float* __restrict__ sinb,
                           const float* __restrict__ qw,
                           const float* __restrict__ kw,
                           const float* __restrict__ um) {
    int b = blockIdx.x / (NH + NKV);
    int h = blockIdx.x % (NH + NKV);
    int d = threadIdx.x;

    if (h == 0) {
        for (int s = d; s < S; s += HD)
            if (um[b * S + s] > 0.5f) g_pos[b] = s;
    }

    bool isq = (h < NH);
    float t = isq ? g_qkv[b][h * HD + d]
                  : g_qkv[b][NQ + (h - NH) * HD + d];

    float sq = t * t;
#pragma unroll
    for (int o = 16; o; o >>= 1) sq += __shfl_xor_sync(0xffffffffu, sq, o);
    __shared__ float sred[4];
    __shared__ float sn[HD];
    if ((d & 31) == 0) sred[d >> 5] = sq;
    __syncthreads();
    float tot = sred[0] + sred[1] + sred[2] + sred[3];
    float w = isq ? qw[d] : kw[d];
    float n = t * rsqrtf(tot * (1.0f / HD) + EPS) * w;
    sn[d] = n;
    __syncthreads();
    float rot = (d < HD / 2) ? -sn[d + HD / 2] : sn[d - HD / 2];
    float outv = n * cosb[b * HD + d] + rot * sinb[b * HD + d];
    if (isq) g_q[b][h][d] = outv;
    else     g_kn[b][h - NH][d] = outv;
}

// ---------------------------------------------------------------------------
// 3. Fused flash-decode chunk kernel + tail combine. Grid 512, 256 threads.
// ---------------------------------------------------------------------------
__global__ __launch_bounds__(256) void k_attn(const float* __restrict__ kcache,
                                              const float* __restrict__ vcache,
                                              const float* __restrict__ kpm,
                                              float* __restrict__ outk,
                                              float* __restrict__ outv) {
    int id    = blockIdx.x;
    int chunk = id & (SC - 1);
    int kvh   = (id >> 2) & (NKV - 1);
    int b     = id >> 5;
    int s0    = chunk * SLEN;
    int t     = threadIdx.x;   // 256

    __shared__ float q0s[HD], q1s[HD], kns[HD], vns[HD];
    __shared__ __align__(16) float e0[SLEN], e1[SLEN];
    __shared__ float sr0[8], sr1[8];
    __shared__ int s_last;

    if (t < HD) {
        q0s[t] = g_q[b][2 * kvh][t];
        q1s[t] = g_q[b][2 * kvh + 1][t];
        kns[t] = g_kn[b][kvh][t];
        vns[t] = g_qkv[b][NQ + DKV + kvh * HD + t];
    }
    __syncthreads();

    int posb = g_pos[b];
    size_t rowbase = ((size_t)(b * DKV + kvh * HD) * S + s0) >> 2; // float4 idx

    // ---- Phase 1: K copy + scores. Thread t owns float4 column t (256 cols),
    //      loops all HD=128 rows (R2 k_scores structure: proven 74% DRAM).
    {
        int c   = t;                 // 0..CF4-1
        int gs  = s0 + (c << 2);
        int rel = posb - gs;
        const float4* src = (const float4*)kcache + rowbase + c;
        float4*       dst = (float4*)outk + rowbase + c;

        float a00 = 0, a01 = 0, a02 = 0, a03 = 0;
        float a10 = 0, a11 = 0, a12 = 0, a13 = 0;
#pragma unroll 4
        for (int d = 0; d < HD; d++) {
            float4 v = src[(size_t)d * (S / 4)];
            if ((unsigned)rel < 4u) (&v.x)[rel] = kns[d];
            dst[(size_t)d * (S / 4)] = v;
            float q0 = q0s[d], q1 = q1s[d];
            a00 += q0 * v.x; a01 += q0 * v.y; a02 += q0 * v.z; a03 += q0 * v.w;
            a10 += q1 * v.x; a11 += q1 * v.y; a12 += q1 * v.z; a13 += q1 * v.w;
        }

        float4 m = *(const float4*)(kpm + (size_t)b * S + gs);
        *(float4*)&e0[c << 2] = make_float4(
            a00 * SCALE + m.x, a01 * SCALE + m.y,
            a02 * SCALE + m.z, a03 * SCALE + m.w);
        *(float4*)&e1[c << 2] = make_float4(
            a10 * SCALE + m.x, a11 * SCALE + m.y,
            a12 * SCALE + m.z, a13 * SCALE + m.w);
        __syncthreads();
    }

    // ---- Phase 2: local softmax over the chunk (two heads)
    {
        float m0 = -1e30f, m1 = -1e30f;
        for (int s = t; s < SLEN; s += 256) {
            m0 = fmaxf(m0, e0[s]);
            m1 = fmaxf(m1, e1[s]);
        }
#pragma unroll
        for (int o = 16; o; o >>= 1) {
            m0 = fmaxf(m0, __shfl_xor_sync(0xffffffffu, m0, o));
            m1 = fmaxf(m1, __shfl_xor_sync(0xffffffffu, m1, o));
        }
        if ((t & 31) == 0) { sr0[t >> 5] = m0; sr1[t >> 5] = m1; }
        __syncthreads();
        m0 = sr0[0]; m1 = sr1[0];
#pragma unroll
        for (int w = 1; w < 8; w++) {
            m0 = fmaxf(m0, sr0[w]);
            m1 = fmaxf(m1, sr1[w]);
        }
        __syncthreads();

        float s0a = 0.0f, s1a = 0.0f;
        for (int s = t; s < SLEN; s += 256) {
            float x0 = __expf(e0[s] - m0); e0[s] = x0; s0a += x0;
            float x1 = __expf(e1[s] - m1); e1[s] = x1; s1a += x1;
        }
#pragma unroll
        for (int o = 16; o; o >>= 1) {
            s0a += __shfl_xor_sync(0xffffffffu, s0a, o);
            s1a += __shfl_xor_sync(0xffffffffu, s1a, o);
        }
        if ((t & 31) == 0) { sr0[t >> 5] = s0a; sr1[t >> 5] = s1a; }
        __syncthreads();
        if (t == 0) {
            float t0 = 0, t1 = 0;
#pragma unroll
            for (int w = 0; w < 8; w++) { t0 += sr0[w]; t1 += sr1[w]; }
            g_ms[b][2 * kvh][chunk]     = make_float2(m0, t0);
            g_ms[b][2 * kvh + 1][chunk] = make_float2(m1, t1);
        }
        __syncthreads();
    }

    // ---- Phase 3: V copy + partial weighted sums. Warp w owns d rows w,w+8,..
    //      e0/e1 read as float4 (LDS.128, conflict-free). 8 loads in flight/d.
    {
        int warp = t >> 5, lane = t & 31;
        const float4* src = (const float4*)vcache + rowbase;
        float4*       dst = (float4*)outv + rowbase;

        for (int d = warp; d < HD; d += 8) {
            float p0 = 0.0f, p1 = 0.0f;
            size_t rb = (size_t)d * (S / 4);
#pragma unroll
            for (int it = 0; it < CF4 / 32; it++) {
                int si = it * 32 + lane;
                float4 v = src[rb + si];
                int sl = si << 2;
                int rel = posb - (s0 + sl);
                if ((unsigned)rel < 4u) (&v.x)[rel] = vns[d];
                dst[rb + si] = v;
                float4 w0 = *(const float4*)&e0[sl];
                float4 w1 = *(const float4*)&e1[sl];
                p0 += w0.x * v.x + w0.y * v.y + w0.z * v.z + w0.w * v.w;
                p1 += w1.x * v.x + w1.y * v.y + w1.z * v.z + w1.w * v.w;
            }
#pragma unroll
            for (int o = 16; o; o >>= 1) {
                p0 += __shfl_xor_sync(0xffffffffu, p0, o);
                p1 += __shfl_xor_sync(0xffffffffu, p1, o);
            }
            if (lane == 0) {
                g_pout[b][2 * kvh][chunk][d]     = p0;
                g_pout[b][2 * kvh + 1][chunk][d] = p1;
            }
        }
    }

    // ---- Tail: last chunk block for this (b,kvh) combines all SC chunks.
    //      (publish g_pout/g_ms, then counter handshake)
    __threadfence();
    __syncthreads();
    if (t == 0) s_last = atomicAdd(&g_cnt[b][kvh], 1);
    __syncthreads();
    if (s_last == SC - 1) {
        __threadfence();                 // acquire side: other blocks' writes
        int h = 2 * kvh + (t >> 7);      // threads 0..127 -> head0, 128..255 -> head1
        int d = t & (HD - 1);

        float2 ms[SC];
        float po[SC];
        float M = -1e30f;
#pragma unroll
        for (int c = 0; c < SC; c++) {
            ms[c] = g_ms[b][h][c];
            po[c] = g_pout[b][h][c][d];
            M = fmaxf(M, ms[c].x);
        }
        float tot = 0.0f, acc = 0.0f;
#pragma unroll
        for (int c = 0; c < SC; c++) {
            float w = __expf(ms[c].x - M);
            tot += w * ms[c].y;
            acc += w * po[c];
        }
        g_attnout[b][h * HD + d] = acc / tot;
        if (t == 0) g_cnt[b][kvh] = 0;   // reset for next graph replay
    }
}

// ---------------------------------------------------------------------------
// 4. Output projection, smem-tiled. Grid HID/8 = 128 blocks, 256 threads.
// ---------------------------------------------------------------------------
__global__ __launch_bounds__(256) void k_oproj(const float* __restrict__ Wo,
                                               float* __restrict__ out) {
    int warp = threadIdx.x >> 5, lane = threadIdx.x & 31;
    int j = blockIdx.x * 8 + warp;
    const float4* w4 = (const float4*)(Wo + (size_t)j * NQ);

    __shared__ __align__(16) float4 s_att[B][128];   // one quarter: 32 KB

    float acc[B];
#pragma unroll
    for (int b = 0; b < B; b++) acc[b] = 0.0f;

#pragma unroll
    for (int q = 0; q < 4; q++) {
        __syncthreads();   // previous quarter fully consumed before overwrite
        for (int i = threadIdx.x; i < B * 128; i += 256) {
            int b = i >> 7, c = i & 127;
            s_att[b][c] = *(const float4*)&g_attnout[b][q * 512 + (c << 2)];
        }
        __syncthreads();
#pragma unroll
        for (int i = 0; i < 4; i++) {
            float4 w = w4[q * 128 + i * 32 + lane];
#pragma unroll
            for (int b = 0; b < B; b++) {
                float4 a = s_att[b][i * 32 + lane];
                acc[b] += w.x * a.x + w.y * a.y + w.z * a.z + w.w * a.w;
            }
        }
    }

#pragma unroll
    for (int b = 0; b < B; b++) {
        float v = acc[b];
#pragma unroll
        for (int o = 16; o; o >>= 1) v += __shfl_xor_sync(0xffffffffu, v, o);
        acc[b] = v;
    }
    if (lane == 0) {
#pragma unroll
        for (int b = 0; b < B; b++) out[b * HID + j] = acc[b];
    }
}

// ---------------------------------------------------------------------------
// Launch
// ---------------------------------------------------------------------------
extern "C" void kernel_launch(void* const* d_in, const int* in_sizes, int n_in,
                              void* d_out, int out_size) {
    (void)in_sizes; (void)n_in; (void)out_size;
    const float* x   = (const float*)d_in[0];
    const float* rc  = (const float*)d_in[1];
    const float* rs  = (const float*)d_in[2];
    const float* kpm = (const float*)d_in[3];
    const float* um  = (const float*)d_in[4];
    const float* kc  = (const float*)d_in[5];
    const float* vc  = (const float*)d_in[6];
    const float* Wq  = (const float*)d_in[7];
    const float* Wk  = (const float*)d_in[8];
    const float* Wv  = (const float*)d_in[9];
    const float* Wo  = (const float*)d_in[10];
    const float* qw  = (const float*)d_in[11];
    const float* kw  = (const float*)d_in[12];

    float* out  = (float*)d_out;
    float* outk = out + (size_t)B * HID;
    float* outv = outk + (size_t)B * DKV * S;

    k_qkv<<<QKV_ROWS, 128>>>(x, Wq, Wk, Wv);
    k_normrope<<<B * (NH + NKV), HD>>>(rc, rs, qw, kw, um);
    k_attn<<<B * NKV * SC, 256>>>(kc, vc, kpm, outk, outv);
    k_oproj<<<HID / 8, 256>>>(Wo, out);
}

// round 13
// speedup vs baseline: 1.0169x; 1.0136x over previous
#include <cuda_runtime.h>

// ---------------------------------------------------------------------------
// TalkerAttentionV2: single-token GQA decode attention + full KV-cache copy.
// B=16, HID=1024, NH=16, NKV=8, HD=128, S=4096.
// R13 = R12 (tail-fused combine) + k_oproj middle ground: 512 blocks x 2
// j-rows, direct loads (R8 structure). R8 1024-blk version was L2-bound on
// attnout re-reads (128MB); R12 128-blk version was parallelism-starved on
// Wo (581 GB/s). This halves attnout traffic while keeping Wo parallelism.
// No cache hints (regressed 2x); no occupancy caps on k_attn (register cliff).
// ---------------------------------------------------------------------------

namespace {
constexpr int B    = 16;
constexpr int HID  = 1024;
constexpr int NH   = 16;
constexpr int NKV  = 8;
constexpr int HD   = 128;
constexpr int S    = 4096;
constexpr int DKV  = NKV * HD;          // 1024
constexpr int NQ   = NH * HD;           // 2048
constexpr int QKV_ROWS = NQ + 2 * DKV;  // 4096
constexpr float EPS = 1e-6f;
constexpr float SCALE = 0.0883883476483184405f; // 128^-0.5
constexpr int SC   = 4;                 // S chunks per (b,kvh) -> 512 blocks
constexpr int SLEN = S / SC;            // 1024
constexpr int CF4  = SLEN / 4;          // 256 float4 columns per chunk
}

// Scratch (static device globals)
__device__ __align__(16) float g_qkv[B][QKV_ROWS];      // raw q|k|v projections
__device__ __align__(16) float g_q[B][NH][HD];          // normed+roped q
__device__ __align__(16) float g_kn[B][NKV][HD];        // normed+roped new k
__device__ __align__(16) float g_pout[B][NH][SC][HD];   // partial V-weighted sums
__device__ __align__(16) float2 g_ms[B][NH][SC];        // per-chunk (max, sumexp)
__device__ __align__(16) float g_attnout[B][NQ];        // combined attention out
__device__ int g_pos[B];
__device__ int g_cnt[B][NKV];                           // zero-init; elected block resets

// ---------------------------------------------------------------------------
// 1. QKV projection: one block per output row (4096 rows), 16 batches at once
// ---------------------------------------------------------------------------
__global__ void k_qkv(const float* __restrict__ x,
                      const float* __restrict__ Wq,
                      const float* __restrict__ Wk,
                      const float* __restrict__ Wv) {
    int r = blockIdx.x;
    const float* wrow;
    if (r < NQ)            wrow = Wq + (size_t)r * HID;
    else if (r < NQ + DKV) wrow = Wk + (size_t)(r - NQ) * HID;
    else                   wrow = Wv + (size_t)(r - NQ - DKV) * HID;

    const float4* w4 = (const float4*)wrow;
    const float4* x4 = (const float4*)x;

    float acc[B];
#pragma unroll
    for (int b = 0; b < B; b++) acc[b] = 0.0f;

#pragma unroll
    for (int i = 0; i < 2; i++) {
        int k = threadIdx.x + i * 128;      // 256 float4 per row
        float4 w = w4[k];
#pragma unroll
        for (int b = 0; b < B; b++) {
            float4 xv = x4[b * (HID / 4) + k];
            acc[b] += w.x * xv.x + w.y * xv.y + w.z * xv.z + w.w * xv.w;
        }
    }

    __shared__ float red[4][B];
    int lane = threadIdx.x & 31, warp = threadIdx.x >> 5;
#pragma unroll
    for (int b = 0; b < B; b++) {
        float v = acc[b];
#pragma unroll
        for (int o = 16; o; o >>= 1) v += __shfl_xor_sync(0xffffffffu, v, o);
        if (lane == 0) red[warp][b] = v;
    }
    __syncthreads();
    if (threadIdx.x < B) {
        float v = red[0][threadIdx.x] + red[1][threadIdx.x] +
                  red[2][threadIdx.x] + red[3][threadIdx.x];
        g_qkv[threadIdx.x][r] = v;
    }
}

// ---------------------------------------------------------------------------
// 2. RMSNorm + RoPE for q and k heads; h==0 blocks also scan the one-hot
//    update mask for pos[b]. One block per (b, head), 128 threads.
// ---------------------------------------------------------------------------
__global__ void k_normrope(const float* __restrict__ cosb,
                           const float* __restrict__ sinb,
                           const float* __restrict__ qw,
                           const float* __restrict__ kw,
                           const float* __restrict__ um) {
    int b = blockIdx.x / (NH + NKV);
    int h = blockIdx.x % (NH + NKV);
    int d = threadIdx.x;

    if (h == 0) {
        for (int s = d; s < S; s += HD)
            if (um[b * S + s] > 0.5f) g_pos[b] = s;
    }

    bool isq = (h < NH);
    float t = isq ? g_qkv[b][h * HD + d]
                  : g_qkv[b][NQ + (h - NH) * HD + d];

    float sq = t * t;
#pragma unroll
    for (int o = 16; o; o >>= 1) sq += __shfl_xor_sync(0xffffffffu, sq, o);
    __shared__ float sred[4];
    __shared__ float sn[HD];
    if ((d & 31) == 0) sred[d >> 5] = sq;
    __syncthreads();
    float tot = sred[0] + sred[1] + sred[2] + sred[3];
    float w = isq ? qw[d] : kw[d];
    float n = t * rsqrtf(tot * (1.0f / HD) + EPS) * w;
    sn[d] = n;
    __syncthreads();
    float rot = (d < HD / 2) ? -sn[d + HD / 2] : sn[d - HD / 2];
    float outv = n * cosb[b * HD + d] + rot * sinb[b * HD + d];
    if (isq) g_q[b][h][d] = outv;
    else     g_kn[b][h - NH][d] = outv;
}

// ---------------------------------------------------------------------------
// 3. Fused flash-decode chunk kernel + tail combine. Grid 512, 256 threads.
// ---------------------------------------------------------------------------
__global__ __launch_bounds__(256) void k_attn(const float* __restrict__ kcache,
                                              const float* __restrict__ vcache,
                                              const float* __restrict__ kpm,
                                              float* __restrict__ outk,
                                              float* __restrict__ outv) {
    int id    = blockIdx.x;
    int chunk = id & (SC - 1);
    int kvh   = (id >> 2) & (NKV - 1);
    int b     = id >> 5;
    int s0    = chunk * SLEN;
    int t     = threadIdx.x;   // 256

    __shared__ float q0s[HD], q1s[HD], kns[HD], vns[HD];
    __shared__ __align__(16) float e0[SLEN], e1[SLEN];
    __shared__ float sr0[8], sr1[8];
    __shared__ int s_last;

    if (t < HD) {
        q0s[t] = g_q[b][2 * kvh][t];
        q1s[t] = g_q[b][2 * kvh + 1][t];
        kns[t] = g_kn[b][kvh][t];
        vns[t] = g_qkv[b][NQ + DKV + kvh * HD + t];
    }
    __syncthreads();

    int posb = g_pos[b];
    size_t rowbase = ((size_t)(b * DKV + kvh * HD) * S + s0) >> 2; // float4 idx

    // ---- Phase 1: K copy + scores. Thread t owns float4 column t (256 cols),
    //      loops all HD=128 rows (R2 k_scores structure: proven 74% DRAM).
    {
        int c   = t;                 // 0..CF4-1
        int gs  = s0 + (c << 2);
        int rel = posb - gs;
        const float4* src = (const float4*)kcache + rowbase + c;
        float4*       dst = (float4*)outk + rowbase + c;

        float a00 = 0, a01 = 0, a02 = 0, a03 = 0;
        float a10 = 0, a11 = 0, a12 = 0, a13 = 0;
#pragma unroll 4
        for (int d = 0; d < HD; d++) {
            float4 v = src[(size_t)d * (S / 4)];
            if ((unsigned)rel < 4u) (&v.x)[rel] = kns[d];
            dst[(size_t)d * (S / 4)] = v;
            float q0 = q0s[d], q1 = q1s[d];
            a00 += q0 * v.x; a01 += q0 * v.y; a02 += q0 * v.z; a03 += q0 * v.w;
            a10 += q1 * v.x; a11 += q1 * v.y; a12 += q1 * v.z; a13 += q1 * v.w;
        }

        float4 m = *(const float4*)(kpm + (size_t)b * S + gs);
        *(float4*)&e0[c << 2] = make_float4(
            a00 * SCALE + m.x, a01 * SCALE + m.y,
            a02 * SCALE + m.z, a03 * SCALE + m.w);
        *(float4*)&e1[c << 2] = make_float4(
            a10 * SCALE + m.x, a11 * SCALE + m.y,
            a12 * SCALE + m.z, a13 * SCALE + m.w);
        __syncthreads();
    }

    // ---- Phase 2: local softmax over the chunk (two heads)
    {
        float m0 = -1e30f, m1 = -1e30f;
        for (int s = t; s < SLEN; s += 256) {
            m0 = fmaxf(m0, e0[s]);
            m1 = fmaxf(m1, e1[s]);
        }
#pragma unroll
        for (int o = 16; o; o >>= 1) {
            m0 = fmaxf(m0, __shfl_xor_sync(0xffffffffu, m0, o));
            m1 = fmaxf(m1, __shfl_xor_sync(0xffffffffu, m1, o));
        }
        if ((t & 31) == 0) { sr0[t >> 5] = m0; sr1[t >> 5] = m1; }
        __syncthreads();
        m0 = sr0[0]; m1 = sr1[0];
#pragma unroll
        for (int w = 1; w < 8; w++) {
            m0 = fmaxf(m0, sr0[w]);
            m1 = fmaxf(m1, sr1[w]);
        }
        __syncthreads();

        float s0a = 0.0f, s1a = 0.0f;
        for (int s = t; s < SLEN; s += 256) {
            float x0 = __expf(e0[s] - m0); e0[s] = x0; s0a += x0;
            float x1 = __expf(e1[s] - m1); e1[s] = x1; s1a += x1;
        }
#pragma unroll
        for (int o = 16; o; o >>= 1) {
            s0a += __shfl_xor_sync(0xffffffffu, s0a, o);
            s1a += __shfl_xor_sync(0xffffffffu, s1a, o);
        }
        if ((t & 31) == 0) { sr0[t >> 5] = s0a; sr1[t >> 5] = s1a; }
        __syncthreads();
        if (t == 0) {
            float t0 = 0, t1 = 0;
#pragma unroll
            for (int w = 0; w < 8; w++) { t0 += sr0[w]; t1 += sr1[w]; }
            g_ms[b][2 * kvh][chunk]     = make_float2(m0, t0);
            g_ms[b][2 * kvh + 1][chunk] = make_float2(m1, t1);
        }
        __syncthreads();
    }

    // ---- Phase 3: V copy + partial weighted sums. Warp w owns d rows w,w+8,..
    //      e0/e1 read as float4 (LDS.128, conflict-free). 8 loads in flight/d.
    {
        int warp = t >> 5, lane = t & 31;
        const float4* src = (const float4*)vcache + rowbase;
        float4*       dst = (float4*)outv + rowbase;

        for (int d = warp; d < HD; d += 8) {
            float p0 = 0.0f, p1 = 0.0f;
            size_t rb = (size_t)d * (S / 4);
#pragma unroll
            for (int it = 0; it < CF4 / 32; it++) {
                int si = it * 32 + lane;
                float4 v = src[rb + si];
                int sl = si << 2;
                int rel = posb - (s0 + sl);
                if ((unsigned)rel < 4u) (&v.x)[rel] = vns[d];
                dst[rb + si] = v;
                float4 w0 = *(const float4*)&e0[sl];
                float4 w1 = *(const float4*)&e1[sl];
                p0 += w0.x * v.x + w0.y * v.y + w0.z * v.z + w0.w * v.w;
                p1 += w1.x * v.x + w1.y * v.y + w1.z * v.z + w1.w * v.w;
            }
#pragma unroll
            for (int o = 16; o; o >>= 1) {
                p0 += __shfl_xor_sync(0xffffffffu, p0, o);
                p1 += __shfl_xor_sync(0xffffffffu, p1, o);
            }
            if (lane == 0) {
                g_pout[b][2 * kvh][chunk][d]     = p0;
                g_pout[b][2 * kvh + 1][chunk][d] = p1;
            }
        }
    }

    // ---- Tail: last chunk block for this (b,kvh) combines all SC chunks.
    __threadfence();
    __syncthreads();
    if (t == 0) s_last = atomicAdd(&g_cnt[b][kvh], 1);
    __syncthreads();
    if (s_last == SC - 1) {
        __threadfence();                 // acquire side: other blocks' writes
        int h = 2 * kvh + (t >> 7);      // threads 0..127 -> head0, 128..255 -> head1
        int d = t & (HD - 1);

        float2 ms[SC];
        float po[SC];
        float M = -1e30f;
#pragma unroll
        for (int c = 0; c < SC; c++) {
            ms[c] = g_ms[b][h][c];
            po[c] = g_pout[b][h][c][d];
            M = fmaxf(M, ms[c].x);
        }
        float tot = 0.0f, acc = 0.0f;
#pragma unroll
        for (int c = 0; c < SC; c++) {
            float w = __expf(ms[c].x - M);
            tot += w * ms[c].y;
            acc += w * po[c];
        }
        g_attnout[b][h * HD + d] = acc / tot;
        if (t == 0) g_cnt[b][kvh] = 0;   // reset for next graph replay
    }
}

// ---------------------------------------------------------------------------
// 4. Output projection: 512 blocks x 256 threads; block handles j-rows
//    (j, j+512). Direct loads (no smem staging barriers): attnout L2 traffic
//    halves vs 1-row/block while Wo load parallelism stays high.
// ---------------------------------------------------------------------------
__global__ __launch_bounds__(256) void k_oproj(const float* __restrict__ Wo,
                                               float* __restrict__ out) {
    int j0 = blockIdx.x;
    int j1 = blockIdx.x + 512;
    const float4* wa = (const float4*)(Wo + (size_t)j0 * NQ);
    const float4* wb = (const float4*)(Wo + (size_t)j1 * NQ);

    float acc0[B], acc1[B];
#pragma unroll
    for (int b = 0; b < B; b++) { acc0[b] = 0.0f; acc1[b] = 0.0f; }

#pragma unroll
    for (int i = 0; i < 2; i++) {
        int r = threadIdx.x + i * 256;     // 512 float4 per row
        float4 w0 = wa[r];
        float4 w1 = wb[r];
#pragma unroll
        for (int b = 0; b < B; b++) {
            float4 a = *(const float4*)&g_attnout[b][r << 2];
            acc0[b] += w0.x * a.x + w0.y * a.y + w0.z * a.z + w0.w * a.w;
            acc1[b] += w1.x * a.x + w1.y * a.y + w1.z * a.z + w1.w * a.w;
        }
    }

    __shared__ float red[8][B];
    int lane = threadIdx.x & 31, warp = threadIdx.x >> 5;

    // reduce + write j0
#pragma unroll
    for (int b = 0; b < B; b++) {
        float v = acc0[b];
#pragma unroll
        for (int o = 16; o; o >>= 1) v += __shfl_xor_sync(0xffffffffu, v, o);
        if (lane == 0) red[warp][b] = v;
    }
    __syncthreads();
    if (threadIdx.x < B) {
        float v = 0.0f;
#pragma unroll
        for (int w = 0; w < 8; w++) v += red[w][threadIdx.x];
        out[threadIdx.x * HID + j0] = v;
    }
    __syncthreads();

    // reduce + write j1
#pragma unroll
    for (int b = 0; b < B; b++) {
        float v = acc1[b];
#pragma unroll
        for (int o = 16; o; o >>= 1) v += __shfl_xor_sync(0xffffffffu, v, o);
        if (lane == 0) red[warp][b] = v;
    }
    __syncthreads();
    if (threadIdx.x < B) {
        float v = 0.0f;
#pragma unroll
        for (int w = 0; w < 8; w++) v += red[w][threadIdx.x];
        out[threadIdx.x * HID + j1] = v;
    }
}

// ---------------------------------------------------------------------------
// Launch
// ---------------------------------------------------------------------------
extern "C" void kernel_launch(void* const* d_in, const int* in_sizes, int n_in,
                              void* d_out, int out_size) {
    (void)in_sizes; (void)n_in; (void)out_size;
    const float* x   = (const float*)d_in[0];
    const float* rc  = (const float*)d_in[1];
    const float* rs  = (const float*)d_in[2];
    const float* kpm = (const float*)d_in[3];
    const float* um  = (const float*)d_in[4];
    const float* kc  = (const float*)d_in[5];
    const float* vc  = (const float*)d_in[6];
    const float* Wq  = (const float*)d_in[7];
    const float* Wk  = (const float*)d_in[8];
    const float* Wv  = (const float*)d_in[9];
    const float* Wo  = (const float*)d_in[10];
    const float* qw  = (const float*)d_in[11];
    const float* kw  = (const float*)d_in[12];

    float* out  = (float*)d_out;
    float* outk = out + (size_t)B * HID;
    float* outv = outk + (size_t)B * DKV * S;

    k_qkv<<<QKV_ROWS, 128>>>(x, Wq, Wk, Wv);
    k_normrope<<<B * (NH + NKV), HD>>>(rc, rs, qw, kw, um);
    k_attn<<<B * NKV * SC, 256>>>(kc, vc, kpm, outk, outv);
    k_oproj<<<512, 256>>>(Wo, out);
}

// round 14
// speedup vs baseline: 1.0289x; 1.0117x over previous
#include <cuda_runtime.h>

// ---------------------------------------------------------------------------
// TalkerAttentionV2: single-token GQA decode attention + full KV-cache copy.
// B=16, HID=1024, NH=16, NKV=8, HD=128, S=4096.
// R14 = R13 + normrope/pos-scan fused into k_qkv via per-head last-block
// election (R12's proven tail pattern). Kernel chain: qkv -> attn -> oproj.
// No cache hints (regressed 2x); no occupancy caps on k_attn (register cliff).
// ---------------------------------------------------------------------------

namespace {
constexpr int B    = 16;
constexpr int HID  = 1024;
constexpr int NH   = 16;
constexpr int NKV  = 8;
constexpr int HD   = 128;
constexpr int S    = 4096;
constexpr int DKV  = NKV * HD;          // 1024
constexpr int NQ   = NH * HD;           // 2048
constexpr int QKV_ROWS = NQ + 2 * DKV;  // 4096
constexpr float EPS = 1e-6f;
constexpr float SCALE = 0.0883883476483184405f; // 128^-0.5
constexpr int SC   = 4;                 // S chunks per (b,kvh) -> 512 blocks
constexpr int SLEN = S / SC;            // 1024
constexpr int CF4  = SLEN / 4;          // 256 float4 columns per chunk
}

// Scratch (static device globals)
__device__ __align__(16) float g_qkv[B][QKV_ROWS];      // raw q|k|v projections
__device__ __align__(16) float g_q[B][NH][HD];          // normed+roped q
__device__ __align__(16) float g_kn[B][NKV][HD];        // normed+roped new k
__device__ __align__(16) float g_pout[B][NH][SC][HD];   // partial V-weighted sums
__device__ __align__(16) float2 g_ms[B][NH][SC];        // per-chunk (max, sumexp)
__device__ __align__(16) float g_attnout[B][NQ];        // combined attention out
__device__ int g_pos[B];
__device__ int g_cnt[B][NKV];                           // attn tail counters
__device__ int g_hcnt[NH + NKV];                        // qkv tail counters

// ---------------------------------------------------------------------------
// 1. QKV projection + tail-fused RMSNorm/RoPE/pos-scan.
//    One block per output row (4096 rows), 128 threads, 16 batches at once.
//    The 128th-arriving block of each head runs normrope for that head.
// ---------------------------------------------------------------------------
__global__ void k_qkv(const float* __restrict__ x,
                      const float* __restrict__ Wq,
                      const float* __restrict__ Wk,
                      const float* __restrict__ Wv,
                      const float* __restrict__ cosb,
                      const float* __restrict__ sinb,
                      const float* __restrict__ qw,
                      const float* __restrict__ kw,
                      const float* __restrict__ um) {
    int r = blockIdx.x;
    const float* wrow;
    if (r < NQ)            wrow = Wq + (size_t)r * HID;
    else if (r < NQ + DKV) wrow = Wk + (size_t)(r - NQ) * HID;
    else                   wrow = Wv + (size_t)(r - NQ - DKV) * HID;

    const float4* w4 = (const float4*)wrow;
    const float4* x4 = (const float4*)x;

    float acc[B];
#pragma unroll
    for (int b = 0; b < B; b++) acc[b] = 0.0f;

#pragma unroll
    for (int i = 0; i < 2; i++) {
        int k = threadIdx.x + i * 128;      // 256 float4 per row
        float4 w = w4[k];
#pragma unroll
        for (int b = 0; b < B; b++) {
            float4 xv = x4[b * (HID / 4) + k];
            acc[b] += w.x * xv.x + w.y * xv.y + w.z * xv.z + w.w * xv.w;
        }
    }

    __shared__ float red[4][B];
    __shared__ int s_last;
    int lane = threadIdx.x & 31, warp = threadIdx.x >> 5;
#pragma unroll
    for (int b = 0; b < B; b++) {
        float v = acc[b];
#pragma unroll
        for (int o = 16; o; o >>= 1) v += __shfl_xor_sync(0xffffffffu, v, o);
        if (lane == 0) red[warp][b] = v;
    }
    __syncthreads();
    if (threadIdx.x < B) {
        float v = red[0][threadIdx.x] + red[1][threadIdx.x] +
                  red[2][threadIdx.x] + red[3][threadIdx.x];
        g_qkv[threadIdx.x][r] = v;
    }

    // ---- Tail: per-head last-block election runs RMSNorm+RoPE.
    if (r >= NQ + DKV) return;           // V rows need no norm
    int head = r >> 7;                   // 0..15 q heads, 16..23 k heads

    __threadfence();
    __syncthreads();
    if (threadIdx.x == 0) s_last = atomicAdd(&g_hcnt[head], 1);
    __syncthreads();
    if (s_last != HD - 1) return;
    __threadfence();                     // acquire: other blocks' g_qkv writes

    // pos scan: q-head h scans the one-hot mask for batch b=h
    if (head < NH) {
        for (int s = threadIdx.x; s < S; s += 128)
            if (um[head * S + s] > 0.5f) g_pos[head] = s;
    }

    bool isq = (head < NH);
    int rowbase = isq ? head * HD : NQ + (head - NH) * HD;
    const float* wv = isq ? qw : kw;
    float4 wreg = *(const float4*)(wv + lane * 4);
    float sgn = (lane < 16) ? -1.0f : 1.0f;   // rotate-half sign

    for (int bb = warp; bb < B; bb += 4) {
        float4 v = *(const float4*)&g_qkv[bb][rowbase + lane * 4];
        float sq = v.x * v.x + v.y * v.y + v.z * v.z + v.w * v.w;
#pragma unroll
        for (int o = 16; o; o >>= 1) sq += __shfl_xor_sync(0xffffffffu, sq, o);
        float rn = rsqrtf(sq * (1.0f / HD) + EPS);
        float4 n = make_float4(v.x * rn * wreg.x, v.y * rn * wreg.y,
                               v.z * rn * wreg.z, v.w * rn * wreg.w);
        float4 rot;
        rot.x = sgn * __shfl_xor_sync(0xffffffffu, n.x, 16);
        rot.y = sgn * __shfl_xor_sync(0xffffffffu, n.y, 16);
        rot.z = sgn * __shfl_xor_sync(0xffffffffu, n.z, 16);
        rot.w = sgn * __shfl_xor_sync(0xffffffffu, n.w, 16);
        float4 c  = *(const float4*)(cosb + bb * HD + lane * 4);
        float4 sn = *(const float4*)(sinb + bb * HD + lane * 4);
        float4 o4 = make_float4(n.x * c.x + rot.x * sn.x,
                                n.y * c.y + rot.y * sn.y,
                                n.z * c.z + rot.z * sn.z,
                                n.w * c.w + rot.w * sn.w);
        if (isq) *(float4*)&g_q[bb][head][lane * 4] = o4;
        else     *(float4*)&g_kn[bb][head - NH][lane * 4] = o4;
    }
    if (threadIdx.x == 0) g_hcnt[head] = 0;   // reset for next graph replay
}

// ---------------------------------------------------------------------------
// 2. Fused flash-decode chunk kernel + tail combine. Grid 512, 256 threads.
// ---------------------------------------------------------------------------
__global__ __launch_bounds__(256) void k_attn(const float* __restrict__ kcache,
                                              const float* __restrict__ vcache,
                                              const float* __restrict__ kpm,
                                              float* __restrict__ outk,
                                              float* __restrict__ outv) {
    int id    = blockIdx.x;
    int chunk = id & (SC - 1);
    int kvh   = (id >> 2) & (NKV - 1);
    int b     = id >> 5;
    int s0    = chunk * SLEN;
    int t     = threadIdx.x;   // 256

    __shared__ float q0s[HD], q1s[HD], kns[HD], vns[HD];
    __shared__ __align__(16) float e0[SLEN], e1[SLEN];
    __shared__ float sr0[8], sr1[8];
    __shared__ int s_last;

    if (t < HD) {
        q0s[t] = g_q[b][2 * kvh][t];
        q1s[t] = g_q[b][2 * kvh + 1][t];
        kns[t] = g_kn[b][kvh][t];
        vns[t] = g_qkv[b][NQ + DKV + kvh * HD + t];
    }
    __syncthreads();

    int posb = g_pos[b];
    size_t rowbase = ((size_t)(b * DKV + kvh * HD) * S + s0) >> 2; // float4 idx

    // ---- Phase 1: K copy + scores. Thread t owns float4 column t (256 cols),
    //      loops all HD=128 rows (R2 k_scores structure: proven 74% DRAM).
    {
        int c   = t;                 // 0..CF4-1
        int gs  = s0 + (c << 2);
        int rel = posb - gs;
        const float4* src = (const float4*)kcache + rowbase + c;
        float4*       dst = (float4*)outk + rowbase + c;

        float a00 = 0, a01 = 0, a02 = 0, a03 = 0;
        float a10 = 0, a11 = 0, a12 = 0, a13 = 0;
#pragma unroll 4
        for (int d = 0; d < HD; d++) {
            float4 v = src[(size_t)d * (S / 4)];
            if ((unsigned)rel < 4u) (&v.x)[rel] = kns[d];
            dst[(size_t)d * (S / 4)] = v;
            float q0 = q0s[d], q1 = q1s[d];
            a00 += q0 * v.x; a01 += q0 * v.y; a02 += q0 * v.z; a03 += q0 * v.w;
            a10 += q1 * v.x; a11 += q1 * v.y; a12 += q1 * v.z; a13 += q1 * v.w;
        }

        float4 m = *(const float4*)(kpm + (size_t)b * S + gs);
        *(float4*)&e0[c << 2] = make_float4(
            a00 * SCALE + m.x, a01 * SCALE + m.y,
            a02 * SCALE + m.z, a03 * SCALE + m.w);
        *(float4*)&e1[c << 2] = make_float4(
            a10 * SCALE + m.x, a11 * SCALE + m.y,
            a12 * SCALE + m.z, a13 * SCALE + m.w);
        __syncthreads();
    }

    // ---- Phase 2: local softmax over the chunk (two heads)
    {
        float m0 = -1e30f, m1 = -1e30f;
        for (int s = t; s < SLEN; s += 256) {
            m0 = fmaxf(m0, e0[s]);
            m1 = fmaxf(m1, e1[s]);
        }
#pragma unroll
        for (int o = 16; o; o >>= 1) {
            m0 = fmaxf(m0, __shfl_xor_sync(0xffffffffu, m0, o));
            m1 = fmaxf(m1, __shfl_xor_sync(0xffffffffu, m1, o));
        }
        if ((t & 31) == 0) { sr0[t >> 5] = m0; sr1[t >> 5] = m1; }
        __syncthreads();
        m0 = sr0[0]; m1 = sr1[0];
#pragma unroll
        for (int w = 1; w < 8; w++) {
            m0 = fmaxf(m0, sr0[w]);
            m1 = fmaxf(m1, sr1[w]);
        }
        __syncthreads();

        float s0a = 0.0f, s1a = 0.0f;
        for (int s = t; s < SLEN; s += 256) {
            float x0 = __expf(e0[s] - m0); e0[s] = x0; s0a += x0;
            float x1 = __expf(e1[s] - m1); e1[s] = x1; s1a += x1;
        }
#pragma unroll
        for (int o = 16; o; o >>= 1) {
            s0a += __shfl_xor_sync(0xffffffffu, s0a, o);
            s1a += __shfl_xor_sync(0xffffffffu, s1a, o);
        }
        if ((t & 31) == 0) { sr0[t >> 5] = s0a; sr1[t >> 5] = s1a; }
        __syncthreads();
        if (t == 0) {
            float t0 = 0, t1 = 0;
#pragma unroll
            for (int w = 0; w < 8; w++) { t0 += sr0[w]; t1 += sr1[w]; }
            g_ms[b][2 * kvh][chunk]     = make_float2(m0, t0);
            g_ms[b][2 * kvh + 1][chunk] = make_float2(m1, t1);
        }
        __syncthreads();
    }

    // ---- Phase 3: V copy + partial weighted sums. Warp w owns d rows w,w+8,..
    //      e0/e1 read as float4 (LDS.128, conflict-free). 8 loads in flight/d.
    {
        int warp = t >> 5, lane = t & 31;
        const float4* src = (const float4*)vcache + rowbase;
        float4*       dst = (float4*)outv + rowbase;

        for (int d = warp; d < HD; d += 8) {
            float p0 = 0.0f, p1 = 0.0f;
            size_t rb = (size_t)d * (S / 4);
#pragma unroll
            for (int it = 0; it < CF4 / 32; it++) {
                int si = it * 32 + lane;
                float4 v = src[rb + si];
                int sl = si << 2;
                int rel = posb - (s0 + sl);
                if ((unsigned)rel < 4u) (&v.x)[rel] = vns[d];
                dst[rb + si] = v;
                float4 w0 = *(const float4*)&e0[sl];
                float4 w1 = *(const float4*)&e1[sl];
                p0 += w0.x * v.x + w0.y * v.y + w0.z * v.z + w0.w * v.w;
                p1 += w1.x * v.x + w1.y * v.y + w1.z * v.z + w1.w * v.w;
            }
#pragma unroll
            for (int o = 16; o; o >>= 1) {
                p0 += __shfl_xor_sync(0xffffffffu, p0, o);
                p1 += __shfl_xor_sync(0xffffffffu, p1, o);
            }
            if (lane == 0) {
                g_pout[b][2 * kvh][chunk][d]     = p0;
                g_pout[b][2 * kvh + 1][chunk][d] = p1;
            }
        }
    }

    // ---- Tail: last chunk block for this (b,kvh) combines all SC chunks.
    __threadfence();
    __syncthreads();
    if (t == 0) s_last = atomicAdd(&g_cnt[b][kvh], 1);
    __syncthreads();
    if (s_last == SC - 1) {
        __threadfence();                 // acquire side: other blocks' writes
        int h = 2 * kvh + (t >> 7);      // threads 0..127 -> head0, 128..255 -> head1
        int d = t & (HD - 1);

        float2 ms[SC];
        float po[SC];
        float M = -1e30f;
#pragma unroll
        for (int c = 0; c < SC; c++) {
            ms[c] = g_ms[b][h][c];
            po[c] = g_pout[b][h][c][d];
            M = fmaxf(M, ms[c].x);
        }
        float tot = 0.0f, acc = 0.0f;
#pragma unroll
        for (int c = 0; c < SC; c++) {
            float w = __expf(ms[c].x - M);
            tot += w * ms[c].y;
            acc += w * po[c];
        }
        g_attnout[b][h * HD + d] = acc / tot;
        if (t == 0) g_cnt[b][kvh] = 0;   // reset for next graph replay
    }
}

// ---------------------------------------------------------------------------
// 3. Output projection: 512 blocks x 256 threads; block handles j-rows
//    (j, j+512). Direct loads; attnout stays L1/L2-resident.
// ---------------------------------------------------------------------------
__global__ __launch_bounds__(256) void k_oproj(const float* __restrict__ Wo,
                                               float* __restrict__ out) {
    int j0 = blockIdx.x;
    int j1 = blockIdx.x + 512;
    const float4* wa = (const float4*)(Wo + (size_t)j0 * NQ);
    const float4* wb = (const float4*)(Wo + (size_t)j1 * NQ);

    float acc0[B], acc1[B];
#pragma unroll
    for (int b = 0; b < B; b++) { acc0[b] = 0.0f; acc1[b] = 0.0f; }

#pragma unroll
    for (int i = 0; i < 2; i++) {
        int r = threadIdx.x + i * 256;     // 512 float4 per row
        float4 w0 = wa[r];
        float4 w1 = wb[r];
#pragma unroll
        for (int b = 0; b < B; b++) {
            float4 a = *(const float4*)&g_attnout[b][r << 2];
            acc0[b] += w0.x * a.x + w0.y * a.y + w0.z * a.z + w0.w * a.w;
            acc1[b] += w1.x * a.x + w1.y * a.y + w1.z * a.z + w1.w * a.w;
        }
    }

    __shared__ float red[8][B];
    int lane = threadIdx.x & 31, warp = threadIdx.x >> 5;

    // reduce + write j0
#pragma unroll
    for (int b = 0; b < B; b++) {
        float v = acc0[b];
#pragma unroll
        for (int o = 16; o; o >>= 1) v += __shfl_xor_sync(0xffffffffu, v, o);
        if (lane == 0) red[warp][b] = v;
    }
    __syncthreads();
    if (threadIdx.x < B) {
        float v = 0.0f;
#pragma unroll
        for (int w = 0; w < 8; w++) v += red[w][threadIdx.x];
        out[threadIdx.x * HID + j0] = v;
    }
    __syncthreads();

    // reduce + write j1
#pragma unroll
    for (int b = 0; b < B; b++) {
        float v = acc1[b];
#pragma unroll
        for (int o = 16; o; o >>= 1) v += __shfl_xor_sync(0xffffffffu, v, o);
        if (lane == 0) red[warp][b] = v;
    }
    __syncthreads();
    if (threadIdx.x < B) {
        float v = 0.0f;
#pragma unroll
        for (int w = 0; w < 8; w++) v += red[w][threadIdx.x];
        out[threadIdx.x * HID + j1] = v;
    }
}

// ---------------------------------------------------------------------------
// Launch
// ---------------------------------------------------------------------------
extern "C" void kernel_launch(void* const* d_in, const int* in_sizes, int n_in,
                              void* d_out, int out_size) {
    (void)in_sizes; (void)n_in; (void)out_size;
    const float* x   = (const float*)d_in[0];
    const float* rc  = (const float*)d_in[1];
    const float* rs  = (const float*)d_in[2];
    const float* kpm = (const float*)d_in[3];
    const float* um  = (const float*)d_in[4];
    const float* kc  = (const float*)d_in[5];
    const float* vc  = (const float*)d_in[6];
    const float* Wq  = (const float*)d_in[7];
    const float* Wk  = (const float*)d_in[8];
    const float* Wv  = (const float*)d_in[9];
    const float* Wo  = (const float*)d_in[10];
    const float* qw  = (const float*)d_in[11];
    const float* kw  = (const float*)d_in[12];

    float* out  = (float*)d_out;
    float* outk = out + (size_t)B * HID;
    float* outv = outk + (size_t)B * DKV * S;

    k_qkv<<<QKV_ROWS, 128>>>(x, Wq, Wk, Wv, rc, rs, qw, kw, um);
    k_attn<<<B * NKV * SC, 256>>>(kc, vc, kpm, outk, outv);
    k_oproj<<<512, 256>>>(Wo, out);
}